// round 4
// baseline (speedup 1.0000x reference)
#include <cuda_runtime.h>
#include <cstdint>

#define EMBED_DIM   200
#define QUAD_DIM    50            // float4 chunks per row
#define NUM_LAYERS  3
#define NUM_WALKS   25
#define BATCH       8192
#define ROWS        76            // rows gathered per (pair, side)
#define MAXP        10            // max pairs per CTA
#define SLOTS       (MAXP * 2)    // 20
#define MAX_ENTRIES (SLOTS * ROWS)// 1520
#define NBUCKETS    16
#define NKEYS       (NBUCKETS * 4)
#define THREADS     256
#define GRID        888           // 148 SMs * 6 CTAs -> exactly one wave
#define HEAVY       200           // 8192 = 200*10 + 688*9

// accumulate v*w into one of 5 register accumulators selected by slot-local id
#define FMA4(A, W, V) do { \
    (A).x = fmaf((W), (V).x, (A).x); \
    (A).y = fmaf((W), (V).y, (A).y); \
    (A).z = fmaf((W), (V).z, (A).z); \
    (A).w = fmaf((W), (V).w, (A).w); } while (0)

#define ACCUM(P, V) do { \
    float _w = s_wc[((P) >> 25) & 3]; \
    int _sl = (((P) >> 20) & 31) >> 2; \
    switch (_sl) { \
        case 0: FMA4(a0, _w, (V)); break; \
        case 1: FMA4(a1, _w, (V)); break; \
        case 2: FMA4(a2, _w, (V)); break; \
        case 3: FMA4(a3, _w, (V)); break; \
        default: FMA4(a4, _w, (V)); break; } } while (0)

__global__ __launch_bounds__(THREADS, 6)
void gnp_bucket_kernel(const float* __restrict__ emb,
                       const float* __restrict__ layer_w,
                       const int*   __restrict__ uidx,
                       const int*   __restrict__ iidx,
                       const int*   __restrict__ uwalks,
                       const int*   __restrict__ iwalks,
                       float*       __restrict__ out)
{
    __shared__ unsigned s_entries[MAX_ENTRIES];
    __shared__ unsigned s_sorted[MAX_ENTRIES];
    __shared__ int      s_cnt[NKEYS];
    __shared__ int      s_start[NKEYS + 1];
    __shared__ int      s_pos[NKEYS];
    __shared__ float    s_wc[4];
    __shared__ float4   s_pub[MAXP][QUAD_DIM];
    __shared__ float    s_red[8][5];

    const int t   = threadIdx.x;
    const int bid = blockIdx.x;
    // 200 CTAs carry 10 pairs, 688 carry 9 -> near-perfect SM balance
    const int np        = (bid < HEAVY) ? 10 : 9;
    const int pair_base = (bid < HEAVY) ? bid * 10 : HEAVY * 10 + (bid - HEAVY) * 9;
    const int n_entries = np * 2 * ROWS;

    if (t == 0) {
        float w0 = layer_w[0], w1 = layer_w[1], w2 = layer_w[2], w3 = layer_w[3];
        float m  = fmaxf(fmaxf(w0, w1), fmaxf(w2, w3));
        float e0 = __expf(w0 - m), e1 = __expf(w1 - m);
        float e2 = __expf(w2 - m), e3 = __expf(w3 - m);
        float inv = 1.0f / (e0 + e1 + e2 + e3);
        s_wc[0] = e0 * inv;
        s_wc[1] = e1 * inv * (1.0f / NUM_WALKS);
        s_wc[2] = e2 * inv * (1.0f / NUM_WALKS);
        s_wc[3] = e3 * inv * (1.0f / NUM_WALKS);
    }
    if (t < NKEYS) s_cnt[t] = 0;
    __syncthreads();

    // ---- stage packed entries + histogram (key = bucket*4 + slot%4) ----
    for (int e = t; e < n_entries; e += THREADS) {
        int s    = e / ROWS;            // slot 0..2*np-1
        int r    = e % ROWS;
        int side = s & 1;
        int b    = pair_base + (s >> 1);
        int idx, wc;
        if (r == 0) {
            idx = side ? iidx[b] : uidx[b];
            wc  = 0;
        } else {
            int w = (r - 1) / NUM_LAYERS;
            int l = (r - 1) % NUM_LAYERS;
            const int* walks = side ? iwalks : uwalks;
            idx = walks[(b * NUM_WALKS + w) * (NUM_LAYERS + 1) + l + 1];
            wc  = l + 1;
        }
        unsigned packed = (unsigned)idx | ((unsigned)s << 20) | ((unsigned)wc << 25);
        s_entries[e] = packed;
        atomicAdd(&s_cnt[((idx >> 16) << 2) | (s & 3)], 1);
    }
    __syncthreads();

    if (t == 0) {
        int acc = 0;
        for (int k = 0; k < NKEYS; k++) {
            s_start[k] = acc; s_pos[k] = acc; acc += s_cnt[k];
        }
        s_start[NKEYS] = acc;
    }
    __syncthreads();

    // ---- scatter into bucket-sorted order ----
    for (int e = t; e < n_entries; e += THREADS) {
        unsigned p = s_entries[e];
        int key = (((int)(p & 0xFFFFFu) >> 16) << 2) | ((int)(p >> 20) & 3);
        int pos = atomicAdd(&s_pos[key], 1);
        s_sorted[pos] = p;
    }
    __syncthreads();

    // ---- phase-bucketed gather-accumulate (register accumulators) ----
    const int q = t >> 6;   // quadrant: owns slots s with s%4 == q
    const int j = t & 63;   // float4 chunk; j<50 active
    float4 a0 = make_float4(0.f, 0.f, 0.f, 0.f);
    float4 a1 = a0, a2 = a0, a3 = a0, a4 = a0;
    const float4* __restrict__ emb4 = (const float4*)emb;

    if (j < QUAD_DIM) {
        #pragma unroll 1
        for (int k = 0; k < NBUCKETS; k++) {
            int key = (k << 2) | q;
            int e   = s_start[key];
            int end = s_start[key + 1];
            for (; e + 4 <= end; e += 4) {
                unsigned p0 = s_sorted[e + 0];
                unsigned p1 = s_sorted[e + 1];
                unsigned p2 = s_sorted[e + 2];
                unsigned p3 = s_sorted[e + 3];
                float4 v0 = __ldg(emb4 + (p0 & 0xFFFFFu) * (unsigned)QUAD_DIM + j);
                float4 v1 = __ldg(emb4 + (p1 & 0xFFFFFu) * (unsigned)QUAD_DIM + j);
                float4 v2 = __ldg(emb4 + (p2 & 0xFFFFFu) * (unsigned)QUAD_DIM + j);
                float4 v3 = __ldg(emb4 + (p3 & 0xFFFFFu) * (unsigned)QUAD_DIM + j);
                ACCUM(p0, v0); ACCUM(p1, v1); ACCUM(p2, v2); ACCUM(p3, v3);
            }
            for (; e < end; e++) {
                unsigned p = s_sorted[e];
                float4 v = __ldg(emb4 + (p & 0xFFFFFu) * (unsigned)QUAD_DIM + j);
                ACCUM(p, v);
            }
        }
    }
    __syncthreads();

    // ---- even quadrants (user sides) publish: slot = sl*4+q, pair = sl*2 + q/2 ----
    if (!(q & 1) && j < QUAD_DIM) {
        int ph = q >> 1;
        s_pub[0 * 2 + ph][j] = a0;
        s_pub[1 * 2 + ph][j] = a1;
        s_pub[2 * 2 + ph][j] = a2;
        s_pub[3 * 2 + ph][j] = a3;
        s_pub[4 * 2 + ph][j] = a4;
    }
    __syncthreads();

    // ---- odd quadrants (item sides): per-pair dot products ----
    float pv[5] = {0.f, 0.f, 0.f, 0.f, 0.f};
    if ((q & 1) && j < QUAD_DIM) {
        int ph = (q - 1) >> 1;
        float4 u;
        u = s_pub[0 * 2 + ph][j]; pv[0] = u.x*a0.x + u.y*a0.y + u.z*a0.z + u.w*a0.w;
        u = s_pub[1 * 2 + ph][j]; pv[1] = u.x*a1.x + u.y*a1.y + u.z*a1.z + u.w*a1.w;
        u = s_pub[2 * 2 + ph][j]; pv[2] = u.x*a2.x + u.y*a2.y + u.z*a2.z + u.w*a2.w;
        u = s_pub[3 * 2 + ph][j]; pv[3] = u.x*a3.x + u.y*a3.y + u.z*a3.z + u.w*a3.w;
        u = s_pub[4 * 2 + ph][j]; pv[4] = u.x*a4.x + u.y*a4.y + u.z*a4.z + u.w*a4.w;
    }
    const int warp = t >> 5, lane = t & 31;
    #pragma unroll
    for (int sl = 0; sl < 5; sl++) {
        float v = pv[sl];
        #pragma unroll
        for (int o = 16; o > 0; o >>= 1)
            v += __shfl_down_sync(0xffffffffu, v, o);
        if (lane == 0) s_red[warp][sl] = v;
    }
    __syncthreads();

    // odd quadrant qq in {1,3} spans warps {2qq, 2qq+1}; pair = sl*2 + (qq-1)/2
    if (t < 10) {
        int qq   = 1 + ((t / 5) << 1);
        int sl   = t % 5;
        int pair = sl * 2 + ((qq - 1) >> 1);
        if (pair < np)
            out[pair_base + pair] = s_red[2 * qq][sl] + s_red[2 * qq + 1][sl];
    }
}

extern "C" void kernel_launch(void* const* d_in, const int* in_sizes, int n_in,
                              void* d_out, int out_size)
{
    const float* emb     = (const float*)d_in[0];
    const float* weights = (const float*)d_in[1];
    const int*   uidx    = (const int*)  d_in[2];
    const int*   iidx    = (const int*)  d_in[3];
    const int*   uwalks  = (const int*)  d_in[4];
    const int*   iwalks  = (const int*)  d_in[5];
    float*       out     = (float*)d_out;

    gnp_bucket_kernel<<<GRID, THREADS>>>(emb, weights, uidx, iidx,
                                         uwalks, iwalks, out);
}

// round 5
// speedup vs baseline: 1.7725x; 1.7725x over previous
#include <cuda_runtime.h>
#include <cstdint>

#define EMBED_DIM   200
#define QUAD_DIM    50              // float4 chunks per row
#define NUM_LAYERS  3
#define NUM_WALKS   25
#define BATCH       8192
#define ROWS        76              // rows gathered per (pair, side)
#define PAIRS_CTA   8
#define SLOTS       (PAIRS_CTA * 2) // 16
#define ENTRIES     (SLOTS * ROWS)  // 1216
#define NBUCKETS    8               // idx >> 17
#define NKEYS       (NBUCKETS * SLOTS) // 128
#define THREADS     256
#define GRID        (BATCH / PAIRS_CTA) // 1024 -> one resident wave @ occ 7

#define FMA4(A, W, V) do { \
    (A).x = fmaf((W), (V).x, (A).x); \
    (A).y = fmaf((W), (V).y, (A).y); \
    (A).z = fmaf((W), (V).z, (A).z); \
    (A).w = fmaf((W), (V).w, (A).w); } while (0)

// One sorted run with a fixed accumulator: branch-free hot loop.
#define RUN(ACC, KEY) do { \
    int _e = s_start[(KEY)]; \
    int _end = s_start[(KEY) + 1]; \
    _Pragma("unroll 4") \
    for (; _e < _end; _e++) { \
        unsigned _p = s_sorted[_e]; \
        float _w = s_wc[(_p >> 24) & 3u]; \
        float4 _v = __ldg(emb4 + (_p & 0xFFFFFu) * (unsigned)QUAD_DIM + j); \
        FMA4(ACC, _w, _v); \
    } } while (0)

__global__ __launch_bounds__(THREADS, 7)
void gnp_bucket_kernel(const float* __restrict__ emb,
                       const float* __restrict__ layer_w,
                       const int*   __restrict__ uidx,
                       const int*   __restrict__ iidx,
                       const int*   __restrict__ uwalks,
                       const int*   __restrict__ iwalks,
                       float*       __restrict__ out)
{
    __shared__ unsigned s_entries[ENTRIES];
    __shared__ unsigned s_sorted[ENTRIES];
    __shared__ int      s_cnt[NKEYS];
    __shared__ int      s_scan[NKEYS];
    __shared__ int      s_start[NKEYS + 1];
    __shared__ int      s_pos[NKEYS];
    __shared__ float    s_wc[4];
    __shared__ float    s_red[8][2];

    const int t   = threadIdx.x;
    const int bid = blockIdx.x;
    const int pair_base = bid * PAIRS_CTA;

    if (t == 0) {
        float w0 = layer_w[0], w1 = layer_w[1], w2 = layer_w[2], w3 = layer_w[3];
        float m  = fmaxf(fmaxf(w0, w1), fmaxf(w2, w3));
        float e0 = __expf(w0 - m), e1 = __expf(w1 - m);
        float e2 = __expf(w2 - m), e3 = __expf(w3 - m);
        float inv = 1.0f / (e0 + e1 + e2 + e3);
        s_wc[0] = e0 * inv;
        s_wc[1] = e1 * inv * (1.0f / NUM_WALKS);
        s_wc[2] = e2 * inv * (1.0f / NUM_WALKS);
        s_wc[3] = e3 * inv * (1.0f / NUM_WALKS);
    }
    if (t < NKEYS) s_cnt[t] = 0;
    __syncthreads();

    // ---- stage packed entries + histogram over (bucket, slot) ----
    for (int e = t; e < ENTRIES; e += THREADS) {
        int s    = e / ROWS;            // slot 0..15
        int r    = e % ROWS;
        int side = s & 1;
        int b    = pair_base + (s >> 1);
        int idx, wc;
        if (r == 0) {
            idx = side ? iidx[b] : uidx[b];
            wc  = 0;
        } else {
            int w = (r - 1) / NUM_LAYERS;
            int l = (r - 1) % NUM_LAYERS;
            const int* walks = side ? iwalks : uwalks;
            idx = walks[(b * NUM_WALKS + w) * (NUM_LAYERS + 1) + l + 1];
            wc  = l + 1;
        }
        s_entries[e] = (unsigned)idx | ((unsigned)s << 20) | ((unsigned)wc << 24);
        atomicAdd(&s_cnt[((idx >> 17) << 4) | s], 1);
    }
    __syncthreads();

    // ---- parallel exclusive scan over 128 keys (Hillis-Steele) ----
    if (t < NKEYS) s_scan[t] = s_cnt[t];
    __syncthreads();
    #pragma unroll
    for (int off = 1; off < NKEYS; off <<= 1) {
        int add = 0;
        if (t < NKEYS && t >= off) add = s_scan[t - off];
        __syncthreads();
        if (t < NKEYS) s_scan[t] += add;
        __syncthreads();
    }
    if (t < NKEYS) {
        s_start[t + 1] = s_scan[t];
        int st = (t == 0) ? 0 : s_scan[t - 1];
        s_start[t] = st;   // overwritten consistently: s_start[t] from this thread
        s_pos[t]   = st;
    }
    __syncthreads();

    // ---- scatter into (bucket, slot)-sorted order ----
    for (int e = t; e < ENTRIES; e += THREADS) {
        unsigned p = s_entries[e];
        int key = ((int)((p & 0xFFFFFu) >> 17) << 4) | ((int)(p >> 20) & 15);
        s_sorted[atomicAdd(&s_pos[key], 1)] = p;
    }
    __syncthreads();

    // ---- phase-bucketed gather: quadrant q owns slots 4q..4q+3 ----
    const int q = t >> 6;
    const int j = t & 63;            // float4 chunk; j<50 active
    float4 a0 = make_float4(0.f, 0.f, 0.f, 0.f);
    float4 a1 = a0, a2 = a0, a3 = a0;
    const float4* __restrict__ emb4 = (const float4*)emb;

    if (j < QUAD_DIM) {
        #pragma unroll 1
        for (int k = 0; k < NBUCKETS; k++) {
            int kb = (k << 4) + (q << 2);
            RUN(a0, kb + 0);
            RUN(a1, kb + 1);
            RUN(a2, kb + 2);
            RUN(a3, kb + 3);
        }
    }

    // slots 4q+0/4q+1 = pair 2q (user/item); 4q+2/4q+3 = pair 2q+1
    float p0 = a0.x * a1.x + a0.y * a1.y + a0.z * a1.z + a0.w * a1.w;
    float p1 = a2.x * a3.x + a2.y * a3.y + a2.z * a3.z + a2.w * a3.w;

    #pragma unroll
    for (int o = 16; o > 0; o >>= 1) {
        p0 += __shfl_down_sync(0xffffffffu, p0, o);
        p1 += __shfl_down_sync(0xffffffffu, p1, o);
    }
    const int warp = t >> 5;
    if ((t & 31) == 0) { s_red[warp][0] = p0; s_red[warp][1] = p1; }
    __syncthreads();

    // quadrant qq spans warps 2qq, 2qq+1; pair = 2qq + (t&1)
    if (t < 8) {
        int qq = t >> 1, pr = t & 1;
        out[pair_base + 2 * qq + pr] =
            s_red[2 * qq][pr] + s_red[2 * qq + 1][pr];
    }
}

extern "C" void kernel_launch(void* const* d_in, const int* in_sizes, int n_in,
                              void* d_out, int out_size)
{
    const float* emb     = (const float*)d_in[0];
    const float* weights = (const float*)d_in[1];
    const int*   uidx    = (const int*)  d_in[2];
    const int*   iidx    = (const int*)  d_in[3];
    const int*   uwalks  = (const int*)  d_in[4];
    const int*   iwalks  = (const int*)  d_in[5];
    float*       out     = (float*)d_out;

    gnp_bucket_kernel<<<GRID, THREADS>>>(emb, weights, uidx, iidx,
                                         uwalks, iwalks, out);
}